// round 2
// baseline (speedup 1.0000x reference)
#include <cuda_runtime.h>
#include <cstdint>

#define N_NODES_MAX 100000
#define IN_F 128
#define OUT_F 64
#define NDIV 9
#define CAT_F (NDIV * OUT_F)   // 576

// Scratch: Wh[d][n][o], 9*100000*64 floats = 230.4 MB (static device global: allowed)
__device__ float g_Wh[(size_t)NDIV * N_NODES_MAX * OUT_F];

// ---------------------------------------------------------------------------
// tf32 helpers
// ---------------------------------------------------------------------------
__device__ __forceinline__ unsigned f2tf32(float x) {
    unsigned r;
    asm("cvt.rna.tf32.f32 %0, %1;" : "=r"(r) : "f"(x));
    return r;
}

__device__ __forceinline__ void mma_tf32(float c[4],
                                         unsigned a0, unsigned a1, unsigned a2, unsigned a3,
                                         unsigned b0, unsigned b1) {
    asm volatile(
        "mma.sync.aligned.m16n8k8.row.col.f32.tf32.tf32.f32 "
        "{%0,%1,%2,%3}, {%4,%5,%6,%7}, {%8,%9}, {%0,%1,%2,%3};"
        : "+f"(c[0]), "+f"(c[1]), "+f"(c[2]), "+f"(c[3])
        : "r"(a0), "r"(a1), "r"(a2), "r"(a3), "r"(b0), "r"(b1));
}

// ---------------------------------------------------------------------------
// GEMM: Wh[d, n, o] = (sum_f feature[n,f] * W[d,o,f]) * norm[n]
// Block: 256 threads (8 warps), tile 128 rows x 64 cols, K=128.
// grid = (ceil(N/128), D)
// ---------------------------------------------------------------------------
#define AS_STRIDE 132
#define WS_STRIDE 132
#define GEMM_SMEM_BYTES ((128 * AS_STRIDE + 64 * WS_STRIDE) * 4)

__global__ __launch_bounds__(256, 1)
void gemm_kernel(const float* __restrict__ feature,
                 const float* __restrict__ norm,
                 const float* __restrict__ W,
                 int n_nodes) {
    extern __shared__ float smem[];
    float* As = smem;                       // [128][132]
    float* Ws = smem + 128 * AS_STRIDE;     // [64][132]  Ws[o][f]

    const int d    = blockIdx.y;
    const int row0 = blockIdx.x * 128;
    const int tid  = threadIdx.x;

    // Load A tile: 128 rows x 128 cols of feature (zero-pad past N)
    for (int i = tid; i < 128 * 32; i += 256) {
        int r = i >> 5, c4 = i & 31;
        float4 v = make_float4(0.f, 0.f, 0.f, 0.f);
        int gr = row0 + r;
        if (gr < n_nodes)
            v = *(const float4*)(feature + (size_t)gr * IN_F + c4 * 4);
        float* p = As + r * AS_STRIDE + c4 * 4;
        p[0] = v.x; p[1] = v.y; p[2] = v.z; p[3] = v.w;
    }
    // Load W_d: Ws[o][f] = W[d, o, f]
    for (int i = tid; i < 64 * 32; i += 256) {
        int r = i >> 5, c4 = i & 31;
        float4 v = *(const float4*)(W + ((size_t)d * OUT_F + r) * IN_F + c4 * 4);
        float* p = Ws + r * WS_STRIDE + c4 * 4;
        p[0] = v.x; p[1] = v.y; p[2] = v.z; p[3] = v.w;
    }
    __syncthreads();

    const int warp = tid >> 5, lane = tid & 31;
    const int g = lane >> 2, t = lane & 3;   // groupID / threadID_in_group
    const int m0 = warp * 16;

    float acc[8][4];
#pragma unroll
    for (int nt = 0; nt < 8; nt++) {
        acc[nt][0] = acc[nt][1] = acc[nt][2] = acc[nt][3] = 0.f;
    }

#pragma unroll
    for (int ks = 0; ks < 16; ks++) {
        const int k0 = ks * 8;
        // A fragments (m16n8k8 tf32 layout)
        float a0f = As[(m0 + g)     * AS_STRIDE + k0 + t];
        float a1f = As[(m0 + g + 8) * AS_STRIDE + k0 + t];
        float a2f = As[(m0 + g)     * AS_STRIDE + k0 + t + 4];
        float a3f = As[(m0 + g + 8) * AS_STRIDE + k0 + t + 4];
        unsigned ah0 = f2tf32(a0f), ah1 = f2tf32(a1f), ah2 = f2tf32(a2f), ah3 = f2tf32(a3f);
        unsigned al0 = f2tf32(a0f - __uint_as_float(ah0));
        unsigned al1 = f2tf32(a1f - __uint_as_float(ah1));
        unsigned al2 = f2tf32(a2f - __uint_as_float(ah2));
        unsigned al3 = f2tf32(a3f - __uint_as_float(ah3));

#pragma unroll
        for (int nt = 0; nt < 8; nt++) {
            // B fragments: B[k][n] = Ws[n][k]
            float b0f = Ws[(nt * 8 + g) * WS_STRIDE + k0 + t];
            float b1f = Ws[(nt * 8 + g) * WS_STRIDE + k0 + t + 4];
            unsigned bh0 = f2tf32(b0f), bh1 = f2tf32(b1f);
            unsigned bl0 = f2tf32(b0f - __uint_as_float(bh0));
            unsigned bl1 = f2tf32(b1f - __uint_as_float(bh1));
            // 3-pass split: hi*hi + hi*lo + lo*hi  (~fp32 accuracy)
            mma_tf32(acc[nt], ah0, ah1, ah2, ah3, bh0, bh1);
            mma_tf32(acc[nt], ah0, ah1, ah2, ah3, bl0, bl1);
            mma_tf32(acc[nt], al0, al1, al2, al3, bh0, bh1);
        }
    }

    // Epilogue: scale by norm[row], store to g_Wh[d][row][col] as float2
    const int r0 = row0 + m0 + g;
    const int r1 = r0 + 8;
    float s0 = (r0 < n_nodes) ? norm[r0] : 0.f;
    float s1 = (r1 < n_nodes) ? norm[r1] : 0.f;
#pragma unroll
    for (int nt = 0; nt < 8; nt++) {
        int col = nt * 8 + 2 * t;
        if (r0 < n_nodes) {
            float2 v = make_float2(acc[nt][0] * s0, acc[nt][1] * s0);
            *(float2*)(g_Wh + ((size_t)d * n_nodes + r0) * OUT_F + col) = v;
        }
        if (r1 < n_nodes) {
            float2 v = make_float2(acc[nt][2] * s1, acc[nt][3] * s1);
            *(float2*)(g_Wh + ((size_t)d * n_nodes + r1) * OUT_F + col) = v;
        }
    }
}

// ---------------------------------------------------------------------------
// Scatter: out[dst, div*64 + o] += Wh[div, src, o]
// 16 threads per edge, one float4 gather + one red.global.add.v4 each.
// ---------------------------------------------------------------------------
__global__ __launch_bounds__(256)
void scatter_kernel(const int* __restrict__ src,
                    const int* __restrict__ dst,
                    const int* __restrict__ ediv,
                    float* __restrict__ out,
                    int E, int n_nodes) {
    long long tt = (long long)blockIdx.x * blockDim.x + threadIdx.x;
    long long total = (long long)E * 16;
    if (tt >= total) return;
    int e = (int)(tt >> 4);
    int j = (int)(tt & 15);
    int dv = __ldg(ediv + e);
    int s  = __ldg(src + e);
    int dd = __ldg(dst + e);
    const float4 v = *(const float4*)(g_Wh + ((size_t)dv * n_nodes + s) * OUT_F + j * 4);
    float* p = out + (size_t)dd * CAT_F + dv * OUT_F + j * 4;
    asm volatile("red.global.add.v4.f32 [%0], {%1,%2,%3,%4};"
                 :: "l"(p), "f"(v.x), "f"(v.y), "f"(v.z), "f"(v.w)
                 : "memory");
}

// ---------------------------------------------------------------------------
// Finalize: out = relu(out * norm[n]), in place. float4 per thread.
// ---------------------------------------------------------------------------
__global__ __launch_bounds__(256)
void finalize_kernel(const float* __restrict__ norm,
                     float* __restrict__ out,
                     int n_nodes) {
    long long tt = (long long)blockIdx.x * blockDim.x + threadIdx.x;
    long long total = (long long)n_nodes * (CAT_F / 4);
    if (tt >= total) return;
    int n = (int)(tt / (CAT_F / 4));
    float s = __ldg(norm + n);
    float4* p = (float4*)out + tt;
    float4 v = *p;
    v.x = fmaxf(v.x * s, 0.f);
    v.y = fmaxf(v.y * s, 0.f);
    v.z = fmaxf(v.z * s, 0.f);
    v.w = fmaxf(v.w * s, 0.f);
    *p = v;
}

// ---------------------------------------------------------------------------
extern "C" void kernel_launch(void* const* d_in, const int* in_sizes, int n_in,
                              void* d_out, int out_size) {
    const float* feature = (const float*)d_in[0];
    const float* norm    = (const float*)d_in[1];
    const float* W       = (const float*)d_in[2];
    const int*   src     = (const int*)d_in[3];
    const int*   dst     = (const int*)d_in[4];
    const int*   ediv    = (const int*)d_in[5];
    float* out = (float*)d_out;

    const int n_nodes = in_sizes[1];          // norm is [N,1]
    const int E       = in_sizes[3];          // src is [E]

    static bool attr_done = false;
    if (!attr_done) {
        cudaFuncSetAttribute(gemm_kernel, cudaFuncAttributeMaxDynamicSharedMemorySize,
                             GEMM_SMEM_BYTES);
        attr_done = true;
    }

    // Zero the accumulation target (d_out is poisoned before timing)
    cudaMemsetAsync(d_out, 0, (size_t)out_size * sizeof(float), 0);

    dim3 gg((n_nodes + 127) / 128, NDIV);
    gemm_kernel<<<gg, 256, GEMM_SMEM_BYTES>>>(feature, norm, W, n_nodes);

    long long st = (long long)E * 16;
    scatter_kernel<<<(unsigned)((st + 255) / 256), 256>>>(src, dst, ediv, out, E, n_nodes);

    long long ft = (long long)n_nodes * (CAT_F / 4);
    finalize_kernel<<<(unsigned)((ft + 255) / 256), 256>>>(norm, out, n_nodes);
}